// round 6
// baseline (speedup 1.0000x reference)
#include <cuda_runtime.h>
#include <cuda_fp16.h>
#include <cstdint>

#define DIM 128
#define MSZ (DIM * DIM)

// fp32 tables for direct copies: g_U[e] = map for pos e+1, e in [0,254]
__device__ __align__(16) float g_U[255 * MSZ];
// fp16 images, chunked SW128 layout. B entries: [hi c0 16K][hi c1 16K][lo c0][lo c1]
// g_A16[s] : level-8 entry (pos 256+s), [m][k], HI ONLY (32KB = 16384 halfs)
// g_B16[e] : U[e], [n][k] (right-operand layout), hi+lo (64KB = 32768 halfs)
// g_AW[b]  : W_b^T = U[1+b], [m][k], hi+lo
__device__ __align__(1024) __half g_A16[256 * 16384];
__device__ __align__(1024) __half g_B16[255 * 32768];
__device__ __align__(1024) __half g_AW[2 * 32768];
// expm scratch (fp32 masters)
__device__ __align__(16) float g_Bm[2 * MSZ];
__device__ __align__(16) float g_B2[2 * MSZ];
__device__ __align__(16) float g_B3[2 * MSZ];
__device__ __align__(16) float g_B4[2 * MSZ];
__device__ __align__(16) float g_X0[2 * MSZ];
__device__ __align__(16) float g_X1[2 * MSZ];

#define SW128(o) ((o) ^ (((o) >> 3) & 0x70))

// ------------------------------------------------------------- PTX helpers
__device__ __forceinline__ uint32_t smem_to_u32(const void* p) {
    uint32_t a;
    asm("{ .reg .u64 t; cvta.to.shared.u64 t, %1; cvt.u32.u64 %0, t; }" : "=r"(a) : "l"(p));
    return a;
}
#define MBARRIER_INIT(addr, cnt) \
    asm volatile("mbarrier.init.shared.b64 [%0], %1;" :: "r"((uint32_t)(addr)), "r"((uint32_t)(cnt)) : "memory")
#define MBARRIER_EXPECT_TX(addr, tx) \
    asm volatile("mbarrier.arrive.expect_tx.shared.b64 _, [%0], %1;" :: "r"((uint32_t)(addr)), "r"((uint32_t)(tx)) : "memory")
#define MBARRIER_ARRIVE(addr) \
    asm volatile("mbarrier.arrive.shared.b64 _, [%0];" :: "r"((uint32_t)(addr)) : "memory")
#define MBARRIER_WAIT_PARITY(mbar_smem_addr, phase_parity) do { \
    uint32_t _mbar = (uint32_t)(mbar_smem_addr); \
    uint32_t _parity = (uint32_t)(phase_parity); \
    uint32_t _done; \
    asm volatile("{\n\t.reg .pred p;\n\t" \
        "mbarrier.try_wait.parity.acquire.cta.shared::cta.b64 p, [%1], %2;\n\t" \
        "selp.b32 %0, 1, 0, p;\n\t}" : "=r"(_done) : "r"(_mbar), "r"(_parity) : "memory"); \
    if (!_done) { \
        asm volatile("{\n\t.reg .pred P1;\n\t" \
            "WAIT_LOOP_%=:\n\t" \
            "mbarrier.try_wait.parity.acquire.cta.shared::cta.b64 P1, [%0], %1, 0x989680;\n\t" \
            "@P1 bra.uni WAIT_DONE_%=;\n\t" \
            "bra.uni WAIT_LOOP_%=;\n\t" \
            "WAIT_DONE_%=:\n\t}" :: "r"(_mbar), "r"(_parity) : "memory"); \
    } \
} while (0)
__device__ __forceinline__ void bulk_ld(uint32_t dst, const void* src, uint32_t bytes, uint32_t mbar) {
    asm volatile("cp.async.bulk.shared::cta.global.mbarrier::complete_tx::bytes [%0], [%1], %2, [%3];"
                 :: "r"(dst), "l"(src), "r"(bytes), "r"(mbar) : "memory");
}
#define LDSM4(r0, r1, r2, r3, a) \
    asm volatile("ldmatrix.sync.aligned.m8n8.x4.shared.b16 {%0,%1,%2,%3}, [%4];" \
                 : "=r"(r0), "=r"(r1), "=r"(r2), "=r"(r3) : "r"(a))
#define MMA16816(c0, c1, c2, c3, a0, a1, a2, a3, b0, b1) \
    asm volatile("mma.sync.aligned.m16n8k16.row.col.f32.f16.f16.f32 " \
                 "{%0,%1,%2,%3}, {%4,%5,%6,%7}, {%8,%9}, {%0,%1,%2,%3};" \
                 : "+f"(c0), "+f"(c1), "+f"(c2), "+f"(c3) \
                 : "r"(a0), "r"(a1), "r"(a2), "r"(a3), "r"(b0), "r"(b1))

// hi/lo fp16 split write into a SW128 image (row = m or n; k fast within chunk)
__device__ __forceinline__ void img_put(__half* img, int row, int k, float v) {
    int idx = ((k >> 6) << 13) + (SW128(row * 128 + (k & 63) * 2) >> 1);
    __half h = __float2half_rn(v);
    img[idx] = h;
    img[idx + 16384] = __float2half_rn(v - __half2float(h));
}

// ===========================================================================
// k_chain: entire expm chain, one CTA per matrix, 512 threads, smem images.
// steps: B2,B3,B4 (3 MULs) -> PS init (SIMT) -> 3 Horner -> 6 squarings.
// smem: [0,64K) A image (hi 32K | lo 32K); [64K,128K) B image. Cs aliases A.
// ===========================================================================
#define CH_SMEM 131072

__device__ void splitA_s(const float* __restrict__ A, char* img) {
    __half* p = (__half*)img;
    for (int e = threadIdx.x * 4; e < MSZ; e += 2048) {
        int m = e >> 7, k0 = e & 127;
        float4 v = *(const float4*)&A[e];
        img_put(p, m, k0 + 0, v.x);
        img_put(p, m, k0 + 1, v.y);
        img_put(p, m, k0 + 2, v.z);
        img_put(p, m, k0 + 3, v.w);
    }
}
__device__ void splitB_s(const float* __restrict__ Y, char* img) {
    __half* p = (__half*)img;
    for (int e = threadIdx.x * 4; e < MSZ; e += 2048) {
        int k = e >> 7, n0 = e & 127;
        float4 v = *(const float4*)&Y[e];
        img_put(p, n0 + 0, k, v.x);
        img_put(p, n0 + 1, k, v.y);
        img_put(p, n0 + 2, k, v.z);
        img_put(p, n0 + 3, k, v.w);
    }
}

// 16-warp product: warp (wr 0..3, wc 0..3) does rows 32wr..+32, cols 32wc..+32
__device__ __forceinline__ void prod32(uint32_t aimg, uint32_t bimg,
                                       int wr, int wc, int lane, float acc[2][4][4]) {
    int rA0 = (wr * 32 + (lane & 15)) * 128;
    int seg = (lane >> 4) * 16;
#pragma unroll
    for (int ks = 0; ks < 8; ks++) {
        uint32_t coff = (uint32_t)(ks >> 2) * 16384u;
        int kw2 = (ks & 3) * 32;
        uint32_t a0, a1, a2, a3, a4, a5, a6, a7;
        LDSM4(a0, a1, a2, a3, aimg + coff + (uint32_t)SW128(rA0 + kw2 + seg));
        LDSM4(a4, a5, a6, a7, aimg + coff + (uint32_t)SW128(rA0 + 2048 + kw2 + seg));
#pragma unroll
        for (int ng = 0; ng < 2; ng++) {
            int rB = (wc * 32 + ng * 16 + (lane & 15)) * 128;
            uint32_t b0, b1, b2, b3;
            LDSM4(b0, b1, b2, b3, bimg + coff + (uint32_t)SW128(rB + kw2 + seg));
            MMA16816(acc[0][2 * ng][0], acc[0][2 * ng][1], acc[0][2 * ng][2], acc[0][2 * ng][3],
                     a0, a1, a2, a3, b0, b2);
            MMA16816(acc[0][2 * ng + 1][0], acc[0][2 * ng + 1][1], acc[0][2 * ng + 1][2], acc[0][2 * ng + 1][3],
                     a0, a1, a2, a3, b1, b3);
            MMA16816(acc[1][2 * ng][0], acc[1][2 * ng][1], acc[1][2 * ng][2], acc[1][2 * ng][3],
                     a4, a5, a6, a7, b0, b2);
            MMA16816(acc[1][2 * ng + 1][0], acc[1][2 * ng + 1][1], acc[1][2 * ng + 1][2], acc[1][2 * ng + 1][3],
                     a4, a5, a6, a7, b1, b3);
        }
    }
}

// one chain matmul: D = A@Bsrc (+ horner terms). Bsrc==null -> reuse B image.
// last!=0: leave result in Cs (smem) instead of writing D.
__device__ void chain_mm(const float* A, const float* Bsrc, float* D,
                         int horner, float4 q,
                         const float* Bm, const float* B2, const float* B3,
                         int last, char* img) {
    __syncthreads();
    splitA_s(A, img);
    if (Bsrc) splitB_s(Bsrc, img + 65536);
    __syncthreads();
    int t = threadIdx.x, wid = t >> 5, lane = t & 31, wr = wid >> 2, wc = wid & 3;
    float acc[2][4][4];
#pragma unroll
    for (int i = 0; i < 2; i++)
#pragma unroll
        for (int j = 0; j < 4; j++)
#pragma unroll
            for (int kq = 0; kq < 4; kq++) acc[i][j][kq] = 0.0f;
    uint32_t ib = smem_to_u32(img);
    prod32(ib,          ib + 65536, wr, wc, lane, acc);   // AH * BH
    prod32(ib,          ib + 98304, wr, wc, lane, acc);   // AH * BL
    prod32(ib + 32768,  ib + 65536, wr, wc, lane, acc);   // AL * BH
    if (last) {
        __syncthreads();
        float* Cs = (float*)img;
#pragma unroll
        for (int rt = 0; rt < 2; rt++) {
            int row0 = wr * 32 + rt * 16 + (lane >> 2);
#pragma unroll
            for (int ct = 0; ct < 4; ct++) {
                int col = wc * 32 + ct * 8 + (lane & 3) * 2;
                *(float2*)&Cs[row0 * DIM + col]       = make_float2(acc[rt][ct][0], acc[rt][ct][1]);
                *(float2*)&Cs[(row0 + 8) * DIM + col] = make_float2(acc[rt][ct][2], acc[rt][ct][3]);
            }
        }
        __syncthreads();
        return;
    }
#pragma unroll
    for (int rt = 0; rt < 2; rt++) {
        int row0 = wr * 32 + rt * 16 + (lane >> 2);
#pragma unroll
        for (int ct = 0; ct < 4; ct++) {
            int col = wc * 32 + ct * 8 + (lane & 3) * 2;
            float v0 = acc[rt][ct][0], v1 = acc[rt][ct][1];
            float v2 = acc[rt][ct][2], v3 = acc[rt][ct][3];
            if (horner) {
                int e0 = row0 * DIM + col, e2 = (row0 + 8) * DIM + col;
                v0 += q.y * Bm[e0]     + q.z * B2[e0]     + q.w * B3[e0];
                v1 += q.y * Bm[e0 + 1] + q.z * B2[e0 + 1] + q.w * B3[e0 + 1];
                v2 += q.y * Bm[e2]     + q.z * B2[e2]     + q.w * B3[e2];
                v3 += q.y * Bm[e2 + 1] + q.z * B2[e2 + 1] + q.w * B3[e2 + 1];
                if (row0 == col) v0 += q.x;
                if (row0 == col + 1) v1 += q.x;
                if (row0 + 8 == col) v2 += q.x;
                if (row0 + 8 == col + 1) v3 += q.x;
            }
            *(float2*)&D[row0 * DIM + col]       = make_float2(v0, v1);
            *(float2*)&D[(row0 + 8) * DIM + col] = make_float2(v2, v3);
        }
    }
}

__global__ void __launch_bounds__(512, 1) k_chain(const float* __restrict__ P) {
    extern __shared__ char img[];
    int b = blockIdx.x, t = threadIdx.x;
    const float* Pb = P + (size_t)b * MSZ;
    float* Bm = g_Bm + b * MSZ; float* B2 = g_B2 + b * MSZ;
    float* B3 = g_B3 + b * MSZ; float* B4 = g_B4 + b * MSZ;
    float* X0 = g_X0 + b * MSZ; float* X1 = g_X1 + b * MSZ;

    const float c0 = 1.0f, c1 = 1.0f, c2 = 0.5f, c3 = 1.0f / 6.0f, c4 = 1.0f / 24.0f;
    const float c5 = 1.0f / 120.0f, c6 = 1.0f / 720.0f, c7 = 1.0f / 5040.0f;
    const float c8 = 1.0f / 40320.0f, c9 = 2.75573192e-6f, c10 = 2.75573192e-7f;
    const float c11 = 2.50521084e-8f, c12 = 2.08767570e-9f, c13 = 1.60590438e-10f;
    const float c14 = 1.14707456e-11f, c15 = 7.64716373e-13f, c16 = 4.77947733e-14f;
    float4 qz = make_float4(0, 0, 0, 0);

    for (int e = t; e < MSZ; e += 512) {
        int r = e >> 7, c = e & 127;
        Bm[e] = (Pb[r * DIM + c] - Pb[c * DIM + r]) * (1.0f / 64.0f);
    }
    chain_mm(Bm, Bm, B2, 0, qz, 0, 0, 0, 0, img);
    chain_mm(B2, Bm, B3, 0, qz, 0, 0, 0, 0, img);
    chain_mm(B2, B2, B4, 0, qz, 0, 0, 0, 0, img);
    __syncthreads();
    for (int e = t; e < MSZ; e += 512) {
        int r = e >> 7, c = e & 127;
        float v = c13 * Bm[e] + c14 * B2[e] + c15 * B3[e] + c16 * B4[e];
        if (r == c) v += c12;
        X0[e] = v;
    }
    chain_mm(X0, B4, X1, 1, make_float4(c8, c9, c10, c11), Bm, B2, B3, 0, img);
    chain_mm(X1, 0,  X0, 1, make_float4(c4, c5, c6, c7),  Bm, B2, B3, 0, img);
    chain_mm(X0, 0,  X1, 1, make_float4(c0, c1, c2, c3),  Bm, B2, B3, 0, img);
    chain_mm(X1, X1, X0, 0, qz, 0, 0, 0, 0, img);
    chain_mm(X0, X0, X1, 0, qz, 0, 0, 0, 0, img);
    chain_mm(X1, X1, X0, 0, qz, 0, 0, 0, 0, img);
    chain_mm(X0, X0, X1, 0, qz, 0, 0, 0, 0, img);
    chain_mm(X1, X1, X0, 0, qz, 0, 0, 0, 0, img);
    chain_mm(X0, X0, 0,  0, qz, 0, 0, 0, 1, img);   // result E in Cs

    // transforms: U = E^T   (E = Cs row-major)
    const float* Cs = (const float*)img;
    float* gU = g_U + (size_t)(1 + b) * MSZ;
    for (int e = t; e < MSZ; e += 512) {           // gU[j][i] = Cs[i][j]
        int i = e >> 7, j = e & 127;
        gU[j * DIM + i] = Cs[e];
    }
    __half* aw = g_AW + (size_t)b * 32768;         // A-img[m][k] = U[m][k] = Cs[k*128+m]
    for (int e = t; e < MSZ; e += 512) {
        int k = e >> 7, m = e & 127;
        img_put(aw, m, k, Cs[e]);
    }
    __half* bi = g_B16 + (size_t)(1 + b) * 32768;  // B-img[n][k] = U[k][n] = Cs[n*128+k]
    for (int e = t; e < MSZ; e += 512) {
        int n = e >> 7, k = e & 127;
        img_put(bi, n, k, Cs[e]);
    }
    if (b == 0) {                                   // identity: g_U[0], g_B16[0]
        for (int e = t; e < MSZ; e += 512) {
            int i = e >> 7, j = e & 127;
            g_U[e] = (i == j) ? 1.0f : 0.0f;
            img_put(g_B16, i, j, (i == j) ? 1.0f : 0.0f);  // B-img[n=i][k=j] = I[j][i]
        }
    }
}

// ===========================================================================
// 8-warp product engine (warp tile 32x64): used by ulevel + final
// ===========================================================================
__device__ __forceinline__ void prod64(uint32_t aimg, uint32_t bimg,
                                       int wr, int wc, int lane, float acc[2][8][4]) {
    int rA0 = (wr * 32 + (lane & 15)) * 128;
    int seg = (lane >> 4) * 16;
    int rB = (lane & 15) * 128;
#pragma unroll
    for (int ks = 0; ks < 8; ks++) {
        uint32_t coff = (uint32_t)(ks >> 2) * 16384u;
        int kw2 = (ks & 3) * 32;
        uint32_t a0, a1, a2, a3, a4, a5, a6, a7;
        LDSM4(a0, a1, a2, a3, aimg + coff + (uint32_t)SW128(rA0 + kw2 + seg));
        LDSM4(a4, a5, a6, a7, aimg + coff + (uint32_t)SW128(rA0 + 2048 + kw2 + seg));
#pragma unroll
        for (int ng = 0; ng < 4; ng++) {
            uint32_t b0, b1, b2, b3;
            LDSM4(b0, b1, b2, b3,
                  bimg + coff + (uint32_t)SW128((wc * 4 + ng) * 2048 + rB + kw2 + seg));
            MMA16816(acc[0][2 * ng][0], acc[0][2 * ng][1], acc[0][2 * ng][2], acc[0][2 * ng][3],
                     a0, a1, a2, a3, b0, b2);
            MMA16816(acc[0][2 * ng + 1][0], acc[0][2 * ng + 1][1], acc[0][2 * ng + 1][2], acc[0][2 * ng + 1][3],
                     a0, a1, a2, a3, b1, b3);
            MMA16816(acc[1][2 * ng][0], acc[1][2 * ng][1], acc[1][2 * ng][2], acc[1][2 * ng][3],
                     a4, a5, a6, a7, b0, b2);
            MMA16816(acc[1][2 * ng + 1][0], acc[1][2 * ng + 1][1], acc[1][2 * ng + 1][2], acc[1][2 * ng + 1][3],
                     a4, a5, a6, a7, b1, b3);
        }
    }
}
// same, but A fragments hoisted and two B images (hi+lo) accumulated (k_final)
__device__ __forceinline__ void prod2_64(uint32_t aimg, uint32_t bhi, uint32_t blo,
                                         int wr, int wc, int lane, float acc[2][8][4]) {
    int rA0 = (wr * 32 + (lane & 15)) * 128;
    int seg = (lane >> 4) * 16;
    int rB = (lane & 15) * 128;
#pragma unroll
    for (int ks = 0; ks < 8; ks++) {
        uint32_t coff = (uint32_t)(ks >> 2) * 16384u;
        int kw2 = (ks & 3) * 32;
        uint32_t a0, a1, a2, a3, a4, a5, a6, a7;
        LDSM4(a0, a1, a2, a3, aimg + coff + (uint32_t)SW128(rA0 + kw2 + seg));
        LDSM4(a4, a5, a6, a7, aimg + coff + (uint32_t)SW128(rA0 + 2048 + kw2 + seg));
#pragma unroll
        for (int ng = 0; ng < 4; ng++) {
            uint32_t boff = coff + (uint32_t)SW128((wc * 4 + ng) * 2048 + rB + kw2 + seg);
            uint32_t b0, b1, b2, b3;
            LDSM4(b0, b1, b2, b3, bhi + boff);
            MMA16816(acc[0][2 * ng][0], acc[0][2 * ng][1], acc[0][2 * ng][2], acc[0][2 * ng][3],
                     a0, a1, a2, a3, b0, b2);
            MMA16816(acc[0][2 * ng + 1][0], acc[0][2 * ng + 1][1], acc[0][2 * ng + 1][2], acc[0][2 * ng + 1][3],
                     a0, a1, a2, a3, b1, b3);
            MMA16816(acc[1][2 * ng][0], acc[1][2 * ng][1], acc[1][2 * ng][2], acc[1][2 * ng][3],
                     a4, a5, a6, a7, b0, b2);
            MMA16816(acc[1][2 * ng + 1][0], acc[1][2 * ng + 1][1], acc[1][2 * ng + 1][2], acc[1][2 * ng + 1][3],
                     a4, a5, a6, a7, b1, b3);
            LDSM4(b0, b1, b2, b3, blo + boff);
            MMA16816(acc[0][2 * ng][0], acc[0][2 * ng][1], acc[0][2 * ng][2], acc[0][2 * ng][3],
                     a0, a1, a2, a3, b0, b2);
            MMA16816(acc[0][2 * ng + 1][0], acc[0][2 * ng + 1][1], acc[0][2 * ng + 1][2], acc[0][2 * ng + 1][3],
                     a0, a1, a2, a3, b1, b3);
            MMA16816(acc[1][2 * ng][0], acc[1][2 * ng][1], acc[1][2 * ng][2], acc[1][2 * ng][3],
                     a4, a5, a6, a7, b0, b2);
            MMA16816(acc[1][2 * ng + 1][0], acc[1][2 * ng + 1][1], acc[1][2 * ng + 1][2], acc[1][2 * ng + 1][3],
                     a4, a5, a6, a7, b1, b3);
        }
    }
}
__device__ __forceinline__ void store_frag64(float* __restrict__ C, int wr, int wc, int lane,
                                             float acc[2][8][4]) {
#pragma unroll
    for (int rt = 0; rt < 2; rt++) {
        int row0 = wr * 32 + rt * 16 + (lane >> 2);
#pragma unroll
        for (int ct = 0; ct < 8; ct++) {
            int col = wc * 64 + ct * 8 + (lane & 3) * 2;
            *(float2*)&C[row0 * DIM + col]       = make_float2(acc[rt][ct][0], acc[rt][ct][1]);
            *(float2*)&C[(row0 + 8) * DIM + col] = make_float2(acc[rt][ct][2], acc[rt][ct][3]);
        }
    }
}

// ===========================================================================
// k_ulevel_h: level j entry s: C = W_{s&1} @ U[offPrev + s>>1]  (3-product)
// modeA=0: write fp32 g_U[e] + B-img g_B16[e] (hi/lo)
// modeA=1: write A-img g_A16[s] (hi only)
// ===========================================================================
#define UL_SMEM (1024 + 131072)
__global__ void __launch_bounds__(256, 1) k_ulevel_h(int offPrev, int offCur, int modeA) {
    extern __shared__ char smem[];
    uint32_t sb = smem_to_u32(smem);
    int s = blockIdx.x;
    int t = threadIdx.x, wid = t >> 5, lane = t & 31, wr = wid >> 1, wc = wid & 1;
    int e = offCur + s;
    const char* As = (const char*)(g_AW + (size_t)(s & 1) * 32768);
    const char* Bs = (const char*)(g_B16 + (size_t)(offPrev + (s >> 1)) * 32768);
    if (t == 0) { MBARRIER_INIT(sb + 0, 1); MBARRIER_INIT(sb + 8, 1); }
    __syncthreads();
    uint32_t AH = sb + 1024, BH = AH + 32768, AL = BH + 32768, BL = AL + 32768;
    if (t == 0) {
        MBARRIER_EXPECT_TX(sb + 0, 65536);
        bulk_ld(AH, As, 32768, sb + 0);
        bulk_ld(BH, Bs, 32768, sb + 0);
        MBARRIER_EXPECT_TX(sb + 8, 65536);
        bulk_ld(AL, As + 32768, 32768, sb + 8);
        bulk_ld(BL, Bs + 32768, 32768, sb + 8);
    }
    float acc[2][8][4];
#pragma unroll
    for (int i = 0; i < 2; i++)
#pragma unroll
        for (int j = 0; j < 8; j++)
#pragma unroll
            for (int kq = 0; kq < 4; kq++) acc[i][j][kq] = 0.0f;

    MBARRIER_WAIT_PARITY(sb + 0, 0);
    prod64(AH, BH, wr, wc, lane, acc);
    MBARRIER_WAIT_PARITY(sb + 8, 0);
    prod64(AH, BL, wr, wc, lane, acc);
    prod64(AL, BH, wr, wc, lane, acc);
    __syncthreads();
    float* Cs = (float*)(smem + 1024);
    store_frag64(Cs, wr, wc, lane, acc);
    __syncthreads();
    if (!modeA) {
        float* Ug = g_U + (size_t)e * MSZ;
        for (int i = t * 4; i < MSZ; i += 1024)
            *(float4*)&Ug[i] = *(const float4*)&Cs[i];
        __half* dst = g_B16 + (size_t)e * 32768;
        for (int item = t; item < 2048; item += 256) {
            int n = item & 127, kb = item >> 7;
            __half hv[8], lv[8];
#pragma unroll
            for (int kk = 0; kk < 8; kk++) {
                float v = Cs[(kb * 8 + kk) * DIM + n];
                __half h = __float2half_rn(v);
                hv[kk] = h;
                lv[kk] = __float2half_rn(v - __half2float(h));
            }
            int k0 = kb * 8;
            int idx = ((k0 >> 6) << 13) + (SW128(n * 128 + (k0 & 63) * 2) >> 1);
            *(uint4*)&dst[idx] = *(uint4*)hv;
            *(uint4*)&dst[idx + 16384] = *(uint4*)lv;
        }
    } else {
        __half* dst = g_A16 + (size_t)s * 16384;
        for (int item = t; item < 2048; item += 256) {
            int kb = item & 15, m = item >> 4;
            __half hv[8];
#pragma unroll
            for (int kk = 0; kk < 8; kk++)
                hv[kk] = __float2half_rn(Cs[m * DIM + kb * 8 + kk]);
            int k0 = kb * 8;
            int idx = ((k0 >> 6) << 13) + (SW128(m * 128 + (k0 & 63) * 2) >> 1);
            *(uint4*)&dst[idx] = *(uint4*)hv;
        }
    }
}

// ===========================================================================
// k_final: persistent, 152 CTAs, 8 compute warps + 1 producer warp.
// 2-slot ring, 96KB/slot: [A 32K][Bhi 32K][Blo 32K]. 2 products per position.
// ===========================================================================
#define SLOT_SZ 98304
#define FINAL_SMEM (1024 + 2 * SLOT_SZ)

__global__ void __launch_bounds__(288, 1) k_final(const int* __restrict__ uniq,
                                                  float* __restrict__ out, int n) {
    extern __shared__ char smem[];
    uint32_t sb = smem_to_u32(smem);
    int t = threadIdx.x;
    if (t == 0) {
#pragma unroll
        for (int s = 0; s < 2; s++) {
            MBARRIER_INIT(sb + s * 16, 1);        // full
            MBARRIER_INIT(sb + s * 16 + 8, 256);  // empty
        }
    }
    __syncthreads();

    if (t >= 256) {                 // producer warp
        if (t == 256) {
            unsigned u = 0;
            for (int i = blockIdx.x; i < n; i += gridDim.x) {
                int pos = __ldg(&uniq[i]);
                if (pos < 256) continue;
                int r = pos & 255, qi = (pos >> 8) - 1;
                unsigned s = u & 1, rd = u >> 1;
                if (u >= 2) MBARRIER_WAIT_PARITY(sb + s * 16 + 8, (rd - 1) & 1);
                MBARRIER_EXPECT_TX(sb + s * 16, 98304);
                uint32_t dst = sb + 1024 + s * SLOT_SZ;
                bulk_ld(dst,         g_A16 + (size_t)r * 16384,          32768, sb + s * 16);
                bulk_ld(dst + 32768, g_B16 + (size_t)qi * 32768,         32768, sb + s * 16);
                bulk_ld(dst + 65536, g_B16 + (size_t)qi * 32768 + 16384, 32768, sb + s * 16);
                u++;
            }
        }
        return;
    }

    int wid = t >> 5, lane = t & 31, wr = wid >> 1, wc = wid & 1;
    unsigned u = 0;
    for (int i = blockIdx.x; i < n; i += gridDim.x) {
        int pos = uniq[i];
        float* C = out + (size_t)i * MSZ;
        if (pos < 256) {
            const float* src = g_U + (size_t)(pos - 1) * MSZ;
            for (int e = t * 4; e < MSZ; e += 1024)
                *(float4*)&C[e] = *(const float4*)&src[e];
            continue;
        }
        unsigned s = u & 1, rd = u >> 1;
        u++;
        uint32_t base = sb + 1024 + s * SLOT_SZ;

        float acc[2][8][4];
#pragma unroll
        for (int a = 0; a < 2; a++)
#pragma unroll
            for (int bq = 0; bq < 8; bq++)
#pragma unroll
                for (int c = 0; c < 4; c++) acc[a][bq][c] = 0.0f;

        MBARRIER_WAIT_PARITY(sb + s * 16, rd & 1);
        prod2_64(base, base + 32768, base + 65536, wr, wc, lane, acc);
        MBARRIER_ARRIVE(sb + s * 16 + 8);
        store_frag64(C, wr, wc, lane, acc);
    }
}

// ===========================================================================
extern "C" void kernel_launch(void* const* d_in, const int* in_sizes, int n_in,
                              void* d_out, int out_size) {
    const int* uniq = (const int*)d_in[0];
    const float* P  = (const float*)d_in[1];
    float* out = (float*)d_out;
    int n = in_sizes[0];

    cudaFuncSetAttribute(k_chain, cudaFuncAttributeMaxDynamicSharedMemorySize, CH_SMEM);
    k_chain<<<2, 512, CH_SMEM>>>(P);

    cudaFuncSetAttribute(k_ulevel_h, cudaFuncAttributeMaxDynamicSharedMemorySize, UL_SMEM);
    k_ulevel_h<<<4,   256, UL_SMEM>>>(1, 3, 0);      // level 2
    k_ulevel_h<<<8,   256, UL_SMEM>>>(3, 7, 0);      // level 3
    k_ulevel_h<<<16,  256, UL_SMEM>>>(7, 15, 0);     // level 4
    k_ulevel_h<<<32,  256, UL_SMEM>>>(15, 31, 0);    // level 5
    k_ulevel_h<<<64,  256, UL_SMEM>>>(31, 63, 0);    // level 6
    k_ulevel_h<<<128, 256, UL_SMEM>>>(63, 127, 0);   // level 7
    k_ulevel_h<<<256, 256, UL_SMEM>>>(127, 255, 1);  // level 8 (A-side, hi only)

    cudaFuncSetAttribute(k_final, cudaFuncAttributeMaxDynamicSharedMemorySize, FINAL_SMEM);
    k_final<<<152, 288, FINAL_SMEM>>>(uniq, out, n);
}

// round 7
// speedup vs baseline: 1.3730x; 1.3730x over previous
#include <cuda_runtime.h>
#include <cuda_fp16.h>
#include <cstdint>

#define DIM 128
#define MSZ (DIM * DIM)

// fp32 tables for direct copies: g_U[e] = map for pos e+1, e in [0,254]
__device__ __align__(16) float g_U[255 * MSZ];
// fp16 images, chunked SW128 layout:
//  g_A16[s] : level-8 entry (pos 256+s), [m][k], HI ONLY (32KB = 16384 halfs)
//  g_B16[e] : U[e], [n][k], hi+lo (64KB): [hi c0 16K][hi c1 16K][lo c0][lo c1]
//  g_AW[b]  : W_b^T = U[1+b], [m][k], hi+lo
__device__ __align__(1024) __half g_A16[256 * 16384];
__device__ __align__(1024) __half g_B16[255 * 32768];
__device__ __align__(1024) __half g_AW[2 * 32768];
// expm scratch
__device__ __align__(16) float g_Bm[2 * MSZ];
__device__ __align__(16) float g_B2[2 * MSZ];
__device__ __align__(16) float g_B3[2 * MSZ];
__device__ __align__(16) float g_B4[2 * MSZ];
__device__ __align__(16) float g_X0[2 * MSZ];
__device__ __align__(16) float g_X1[2 * MSZ];
// global barrier state (monotonic across graph replays)
__device__ unsigned g_count = 0;   // k_fused
__device__ unsigned g_count2 = 0;  // k_levels
__device__ unsigned g_epoch = 0;

#define SW128(o) ((o) ^ (((o) >> 3) & 0x70))

// ------------------------------------------------------------- PTX helpers
__device__ __forceinline__ uint32_t smem_to_u32(const void* p) {
    uint32_t a;
    asm("{ .reg .u64 t; cvta.to.shared.u64 t, %1; cvt.u32.u64 %0, t; }" : "=r"(a) : "l"(p));
    return a;
}
#define MBARRIER_INIT(addr, cnt) \
    asm volatile("mbarrier.init.shared.b64 [%0], %1;" :: "r"((uint32_t)(addr)), "r"((uint32_t)(cnt)) : "memory")
#define MBARRIER_EXPECT_TX(addr, tx) \
    asm volatile("mbarrier.arrive.expect_tx.shared.b64 _, [%0], %1;" :: "r"((uint32_t)(addr)), "r"((uint32_t)(tx)) : "memory")
#define MBARRIER_ARRIVE(addr) \
    asm volatile("mbarrier.arrive.shared.b64 _, [%0];" :: "r"((uint32_t)(addr)) : "memory")
#define MBARRIER_WAIT_PARITY(mbar_smem_addr, phase_parity) do { \
    uint32_t _mbar = (uint32_t)(mbar_smem_addr); \
    uint32_t _parity = (uint32_t)(phase_parity); \
    uint32_t _done; \
    asm volatile("{\n\t.reg .pred p;\n\t" \
        "mbarrier.try_wait.parity.acquire.cta.shared::cta.b64 p, [%1], %2;\n\t" \
        "selp.b32 %0, 1, 0, p;\n\t}" : "=r"(_done) : "r"(_mbar), "r"(_parity) : "memory"); \
    if (!_done) { \
        asm volatile("{\n\t.reg .pred P1;\n\t" \
            "WAIT_LOOP_%=:\n\t" \
            "mbarrier.try_wait.parity.acquire.cta.shared::cta.b64 P1, [%0], %1, 0x989680;\n\t" \
            "@P1 bra.uni WAIT_DONE_%=;\n\t" \
            "bra.uni WAIT_LOOP_%=;\n\t" \
            "WAIT_DONE_%=:\n\t}" :: "r"(_mbar), "r"(_parity) : "memory"); \
    } \
} while (0)
__device__ __forceinline__ void bulk_ld(uint32_t dst, const void* src, uint32_t bytes, uint32_t mbar) {
    asm volatile("cp.async.bulk.shared::cta.global.mbarrier::complete_tx::bytes [%0], [%1], %2, [%3];"
                 :: "r"(dst), "l"(src), "r"(bytes), "r"(mbar) : "memory");
}
#define LDSM4(r0, r1, r2, r3, a) \
    asm volatile("ldmatrix.sync.aligned.m8n8.x4.shared.b16 {%0,%1,%2,%3}, [%4];" \
                 : "=r"(r0), "=r"(r1), "=r"(r2), "=r"(r3) : "r"(a))
#define MMA16816(c0, c1, c2, c3, a0, a1, a2, a3, b0, b1) \
    asm volatile("mma.sync.aligned.m16n8k16.row.col.f32.f16.f16.f32 " \
                 "{%0,%1,%2,%3}, {%4,%5,%6,%7}, {%8,%9}, {%0,%1,%2,%3};" \
                 : "+f"(c0), "+f"(c1), "+f"(c2), "+f"(c3) \
                 : "r"(a0), "r"(a1), "r"(a2), "r"(a3), "r"(b0), "r"(b1))

// hi/lo fp16 split write into a SW128 image
__device__ __forceinline__ void img_put(__half* img, int row, int k, float v) {
    int idx = ((k >> 6) << 13) + (SW128(row * 128 + (k & 63) * 2) >> 1);
    __half h = __float2half_rn(v);
    img[idx] = h;
    img[idx + 16384] = __float2half_rn(v - __half2float(h));
}

// ------------------------------------------------- global spin barriers
__device__ __forceinline__ void gbar_on(unsigned* ctr, unsigned target) {
    asm volatile("fence.proxy.async;" ::: "memory");
    __syncthreads();
    if (threadIdx.x == 0) {
        __threadfence();
        atomicAdd(ctr, 1u);
        unsigned v;
        do {
            asm volatile("ld.acquire.gpu.u32 %0, [%1];" : "=r"(v) : "l"(ctr) : "memory");
            if ((int)(v - target) >= 0) break;
            __nanosleep(64);
        } while (true);
    }
    __syncthreads();
}

// ------------------------------------- fp32 64x64 tile engine (.cg loads)
__device__ __forceinline__ void mm64cg(const float* __restrict__ A, const float* __restrict__ B,
                                       int rowBase, int colBase, float acc[4][4]) {
    __shared__ __align__(16) float As[16][64];
    __shared__ __align__(16) float Bs[16][64];
    int t = threadIdx.x;
    int tx = t & 15, ty = t >> 4;
#pragma unroll
    for (int i = 0; i < 4; i++)
#pragma unroll
        for (int j = 0; j < 4; j++) acc[i][j] = 0.0f;
    for (int kc = 0; kc < DIM; kc += 16) {
        {
            int ar = t >> 2, acg = (t & 3) * 4;
            float4 av = __ldcg((const float4*)&A[(rowBase + ar) * DIM + kc + acg]);
            As[acg + 0][ar] = av.x; As[acg + 1][ar] = av.y;
            As[acg + 2][ar] = av.z; As[acg + 3][ar] = av.w;
        }
        {
            int br = t >> 4, bcg = (t & 15) * 4;
            *(float4*)&Bs[br][bcg] = __ldcg((const float4*)&B[(kc + br) * DIM + colBase + bcg]);
        }
        __syncthreads();
#pragma unroll
        for (int kk = 0; kk < 16; kk++) {
            float a[4], bb[4];
            *(float4*)a  = *(const float4*)&As[kk][ty * 4];
            *(float4*)bb = *(const float4*)&Bs[kk][tx * 4];
#pragma unroll
            for (int i = 0; i < 4; i++)
#pragma unroll
                for (int j = 0; j < 4; j++) acc[i][j] += a[i] * bb[j];
        }
        __syncthreads();
    }
}
__device__ __forceinline__ void store64(float* __restrict__ C, int rowBase, int colBase,
                                        float acc[4][4]) {
    int tx = threadIdx.x & 15, ty = threadIdx.x >> 4;
#pragma unroll
    for (int i = 0; i < 4; i++)
#pragma unroll
        for (int j = 0; j < 4; j++)
            C[(rowBase + ty * 4 + i) * DIM + colBase + tx * 4 + j] = acc[i][j];
}

__global__ void k_epoch() { atomicAdd(&g_epoch, 1u); }

// -------------------------------------------------------------------------
// k_fused: prep -> B2,B3,B4 -> PS deg-16 -> 6 squarings -> init tables ->
//          levels 2..5 -> split (AW hi/lo + B16[0..62] hi/lo).  128 CTAs.
// -------------------------------------------------------------------------
#define NBAR 18u
__global__ void __launch_bounds__(256) k_fused(const float* __restrict__ P) {
    const int cta = blockIdx.y * 32 + blockIdx.x;   // 0..127
    const int t = threadIdx.x;
    __shared__ unsigned sE;
    if (t == 0) sE = *(volatile unsigned*)&g_epoch;
    __syncthreads();
    const unsigned base = (sE - 1u) * NBAR * 128u;
    int barId = 0;
#define GBAR() gbar_on(&g_count, base + (unsigned)(++barId) * 128u)

    const float c0 = 1.0f, c1 = 1.0f, c2 = 0.5f, c3 = 1.0f / 6.0f, c4 = 1.0f / 24.0f;
    const float c5 = 1.0f / 120.0f, c6 = 1.0f / 720.0f, c7 = 1.0f / 5040.0f;
    const float c8 = 1.0f / 40320.0f, c9 = 2.75573192e-6f, c10 = 2.75573192e-7f;
    const float c11 = 2.50521084e-8f, c12 = 2.08767570e-9f, c13 = 1.60590438e-10f;
    const float c14 = 1.14707456e-11f, c15 = 7.64716373e-13f, c16 = 4.77947733e-14f;

    {   // prep
        int idx = cta * 256 + t;
        int b = idx >> 14, r = (idx >> 7) & 127, c = idx & 127;
        float h = __ldg(&P[b * MSZ + r * DIM + c]) - __ldg(&P[b * MSZ + c * DIM + r]);
        g_Bm[idx] = h * (1.0f / 64.0f);
    }
    GBAR();
    if (cta < 8) {   // B2
        int b = cta >> 2, quad = cta & 3;
        int rB = (quad >> 1) * 64, cB = (quad & 1) * 64;
        float acc[4][4];
        mm64cg(g_Bm + b * MSZ, g_Bm + b * MSZ, rB, cB, acc);
        store64(g_B2 + b * MSZ, rB, cB, acc);
    }
    GBAR();
    if (cta < 16) {  // B3, B4
        int z = cta >> 3, b = (cta >> 2) & 1, quad = cta & 3;
        int rB = (quad >> 1) * 64, cB = (quad & 1) * 64;
        float acc[4][4];
        mm64cg(g_B2 + b * MSZ, (z ? g_B2 : g_Bm) + b * MSZ, rB, cB, acc);
        store64((z ? g_B4 : g_B3) + b * MSZ, rB, cB, acc);
    }
    GBAR();
    {   // PS init
        int idx = cta * 256 + t;
        int r = (idx >> 7) & 127, c = idx & 127;
        float v = c13 * __ldcg(&g_Bm[idx]) + c14 * __ldcg(&g_B2[idx]) +
                  c15 * __ldcg(&g_B3[idx]) + c16 * __ldcg(&g_B4[idx]);
        if (r == c) v += c12;
        g_X0[idx] = v;
    }
    GBAR();
    {
        float qs[3][4] = {{c8, c9, c10, c11}, {c4, c5, c6, c7}, {c0, c1, c2, c3}};
        int sel = 0;
        for (int h = 0; h < 3; h++) {
            if (cta < 8) {
                int b = cta >> 2, quad = cta & 3;
                int rB = (quad >> 1) * 64, cB = (quad & 1) * 64;
                const float* T = (sel ? g_X1 : g_X0) + b * MSZ;
                float* Y       = (sel ? g_X0 : g_X1) + b * MSZ;
                float acc[4][4];
                mm64cg(T, g_B4 + b * MSZ, rB, cB, acc);
                int tx = t & 15, ty = t >> 4;
#pragma unroll
                for (int i = 0; i < 4; i++) {
                    int gr = rB + ty * 4 + i;
#pragma unroll
                    for (int j = 0; j < 4; j++) {
                        int gc = cB + tx * 4 + j;
                        int e = b * MSZ + gr * DIM + gc;
                        float v = acc[i][j] + qs[h][1] * __ldcg(&g_Bm[e]) +
                                  qs[h][2] * __ldcg(&g_B2[e]) + qs[h][3] * __ldcg(&g_B3[e]);
                        if (gr == gc) v += qs[h][0];
                        Y[gr * DIM + gc] = v;
                    }
                }
            }
            sel ^= 1;
            GBAR();
        }
        for (int sq = 0; sq < 6; sq++) {
            if (cta < 8) {
                int b = cta >> 2, quad = cta & 3;
                int rB = (quad >> 1) * 64, cB = (quad & 1) * 64;
                const float* X = (sel ? g_X1 : g_X0) + b * MSZ;
                float* Y       = (sel ? g_X0 : g_X1) + b * MSZ;
                float acc[4][4];
                mm64cg(X, X, rB, cB, acc);
                store64(Y, rB, cB, acc);
            }
            sel ^= 1;
            GBAR();
        }
    }
    // init tables (E in X1): g_U[0]=I, g_U[1+b]=E_b^T
    for (int i = cta * 256 + t; i < 3 * MSZ; i += 32768) {
        int m = i >> 14, r = (i >> 7) & 127, c = i & 127;
        if (m == 0) g_U[i] = (r == c) ? 1.0f : 0.0f;
        else        g_U[m * MSZ + r * DIM + c] = __ldcg(&g_X1[(m - 1) * MSZ + c * DIM + r]);
    }
    GBAR();
    // levels 2..5
    for (int j = 2; j <= 5; j++) {
        if (cta < (4 << j)) {
            int s = cta >> 2, quad = cta & 3;
            int rB = (quad >> 1) * 64, cB = (quad & 1) * 64;
            const float* A = g_U + (size_t)(1 + (s & 1)) * MSZ;
            const float* B = g_U + (size_t)(((1 << (j - 1)) - 1) + (s >> 1)) * MSZ;
            float* C       = g_U + (size_t)(((1 << j) - 1) + s) * MSZ;
            float acc[4][4];
            mm64cg(A, B, rB, cB, acc);
            store64(C, rB, cB, acc);
        }
        GBAR();
    }
    // split phase: g_AW (U[1],U[2] as [m][k]) + g_B16[0..62] ([n][k]), fp16 hi/lo
    for (int item = cta * 256 + t; item < 2 * MSZ; item += 32768) {
        int mat = item >> 14, el = item & 16383, m = el >> 7, k = el & 127;
        float v = __ldcg(&g_U[(size_t)(1 + mat) * MSZ + m * DIM + k]);
        img_put(g_AW + (size_t)mat * 32768, m, k, v);
    }
    for (int item = cta * 256 + t; item < 63 * MSZ; item += 32768) {
        int mat = item >> 14, el = item & 16383, n = el & 127, k = el >> 7;
        float v = __ldcg(&g_U[(size_t)mat * MSZ + k * DIM + n]);
        img_put(g_B16 + (size_t)mat * 32768, n, k, v);
    }
#undef GBAR
}

// ===========================================================================
// 8-warp HMMA engines (warp tile 32x64)
// ===========================================================================
__device__ __forceinline__ void prod64(uint32_t aimg, uint32_t bimg,
                                       int wr, int wc, int lane, float acc[2][8][4]) {
    int rA0 = (wr * 32 + (lane & 15)) * 128;
    int seg = (lane >> 4) * 16;
    int rB = (lane & 15) * 128;
#pragma unroll
    for (int ks = 0; ks < 8; ks++) {
        uint32_t coff = (uint32_t)(ks >> 2) * 16384u;
        int kw2 = (ks & 3) * 32;
        uint32_t a0, a1, a2, a3, a4, a5, a6, a7;
        LDSM4(a0, a1, a2, a3, aimg + coff + (uint32_t)SW128(rA0 + kw2 + seg));
        LDSM4(a4, a5, a6, a7, aimg + coff + (uint32_t)SW128(rA0 + 2048 + kw2 + seg));
#pragma unroll
        for (int ng = 0; ng < 4; ng++) {
            uint32_t b0, b1, b2, b3;
            LDSM4(b0, b1, b2, b3,
                  bimg + coff + (uint32_t)SW128((wc * 4 + ng) * 2048 + rB + kw2 + seg));
            MMA16816(acc[0][2 * ng][0], acc[0][2 * ng][1], acc[0][2 * ng][2], acc[0][2 * ng][3],
                     a0, a1, a2, a3, b0, b2);
            MMA16816(acc[0][2 * ng + 1][0], acc[0][2 * ng + 1][1], acc[0][2 * ng + 1][2], acc[0][2 * ng + 1][3],
                     a0, a1, a2, a3, b1, b3);
            MMA16816(acc[1][2 * ng][0], acc[1][2 * ng][1], acc[1][2 * ng][2], acc[1][2 * ng][3],
                     a4, a5, a6, a7, b0, b2);
            MMA16816(acc[1][2 * ng + 1][0], acc[1][2 * ng + 1][1], acc[1][2 * ng + 1][2], acc[1][2 * ng + 1][3],
                     a4, a5, a6, a7, b1, b3);
        }
    }
}
// A hoisted, two B images (hi+lo) accumulated
__device__ __forceinline__ void prod2_64(uint32_t aimg, uint32_t bhi, uint32_t blo,
                                         int wr, int wc, int lane, float acc[2][8][4]) {
    int rA0 = (wr * 32 + (lane & 15)) * 128;
    int seg = (lane >> 4) * 16;
    int rB = (lane & 15) * 128;
#pragma unroll
    for (int ks = 0; ks < 8; ks++) {
        uint32_t coff = (uint32_t)(ks >> 2) * 16384u;
        int kw2 = (ks & 3) * 32;
        uint32_t a0, a1, a2, a3, a4, a5, a6, a7;
        LDSM4(a0, a1, a2, a3, aimg + coff + (uint32_t)SW128(rA0 + kw2 + seg));
        LDSM4(a4, a5, a6, a7, aimg + coff + (uint32_t)SW128(rA0 + 2048 + kw2 + seg));
#pragma unroll
        for (int ng = 0; ng < 4; ng++) {
            uint32_t boff = coff + (uint32_t)SW128((wc * 4 + ng) * 2048 + rB + kw2 + seg);
            uint32_t b0, b1, b2, b3;
            LDSM4(b0, b1, b2, b3, bhi + boff);
            MMA16816(acc[0][2 * ng][0], acc[0][2 * ng][1], acc[0][2 * ng][2], acc[0][2 * ng][3],
                     a0, a1, a2, a3, b0, b2);
            MMA16816(acc[0][2 * ng + 1][0], acc[0][2 * ng + 1][1], acc[0][2 * ng + 1][2], acc[0][2 * ng + 1][3],
                     a0, a1, a2, a3, b1, b3);
            MMA16816(acc[1][2 * ng][0], acc[1][2 * ng][1], acc[1][2 * ng][2], acc[1][2 * ng][3],
                     a4, a5, a6, a7, b0, b2);
            MMA16816(acc[1][2 * ng + 1][0], acc[1][2 * ng + 1][1], acc[1][2 * ng + 1][2], acc[1][2 * ng + 1][3],
                     a4, a5, a6, a7, b1, b3);
            LDSM4(b0, b1, b2, b3, blo + boff);
            MMA16816(acc[0][2 * ng][0], acc[0][2 * ng][1], acc[0][2 * ng][2], acc[0][2 * ng][3],
                     a0, a1, a2, a3, b0, b2);
            MMA16816(acc[0][2 * ng + 1][0], acc[0][2 * ng + 1][1], acc[0][2 * ng + 1][2], acc[0][2 * ng + 1][3],
                     a0, a1, a2, a3, b1, b3);
            MMA16816(acc[1][2 * ng][0], acc[1][2 * ng][1], acc[1][2 * ng][2], acc[1][2 * ng][3],
                     a4, a5, a6, a7, b0, b2);
            MMA16816(acc[1][2 * ng + 1][0], acc[1][2 * ng + 1][1], acc[1][2 * ng + 1][2], acc[1][2 * ng + 1][3],
                     a4, a5, a6, a7, b1, b3);
        }
    }
}
__device__ __forceinline__ void store_frag64(float* __restrict__ C, int wr, int wc, int lane,
                                             float acc[2][8][4]) {
#pragma unroll
    for (int rt = 0; rt < 2; rt++) {
        int row0 = wr * 32 + rt * 16 + (lane >> 2);
#pragma unroll
        for (int ct = 0; ct < 8; ct++) {
            int col = wc * 64 + ct * 8 + (lane & 3) * 2;
            *(float2*)&C[row0 * DIM + col]       = make_float2(acc[rt][ct][0], acc[rt][ct][1]);
            *(float2*)&C[(row0 + 8) * DIM + col] = make_float2(acc[rt][ct][2], acc[rt][ct][3]);
        }
    }
}

// ===========================================================================
// k_levels: levels 6..8 in ONE launch. 128 persistent CTAs, 2 spin barriers.
// level j entry s: C = W_{s&1} @ U[offPrev + s>>1]  (3-product hi/lo)
// j<8: write fp32 g_U[e] + B-img g_B16[e]; j=8: write A-img g_A16[s] (hi only)
// ===========================================================================
#define NBARL 2u
#define UL_SMEM (1024 + 131072)
__global__ void __launch_bounds__(256, 1) k_levels() {
    extern __shared__ char smem[];
    uint32_t sb = smem_to_u32(smem);
    const int cta = blockIdx.x;     // 0..127
    const int t = threadIdx.x, wid = t >> 5, lane = t & 31, wr = wid >> 1, wc = wid & 1;
    __shared__ unsigned sE;
    if (t == 0) sE = *(volatile unsigned*)&g_epoch;
    __syncthreads();
    const unsigned base = (sE - 1u) * NBARL * 128u;
    int barId = 0;
    if (t == 0) { MBARRIER_INIT(sb + 0, 1); MBARRIER_INIT(sb + 8, 1); }
    __syncthreads();
    uint32_t AH = sb + 1024, BH = AH + 32768, AL = BH + 32768, BL = AL + 32768;
    int ph = 0;

    for (int lvl = 6; lvl <= 8; lvl++) {
        int ntask = 1 << lvl;
        int offPrev = (1 << (lvl - 1)) - 1, offCur = (1 << lvl) - 1;
        for (int s = cta; s < ntask; s += 128) {
            __syncthreads();   // images free for reuse
            int e = offCur + s;
            const char* As = (const char*)(g_AW + (size_t)(s & 1) * 32768);
            const char* Bs = (const char*)(g_B16 + (size_t)(offPrev + (s >> 1)) * 32768);
            if (t == 0) {
                MBARRIER_EXPECT_TX(sb + 0, 65536);
                bulk_ld(AH, As, 32768, sb + 0);
                bulk_ld(BH, Bs, 32768, sb + 0);
                MBARRIER_EXPECT_TX(sb + 8, 65536);
                bulk_ld(AL, As + 32768, 32768, sb + 8);
                bulk_ld(BL, Bs + 32768, 32768, sb + 8);
            }
            float acc[2][8][4];
#pragma unroll
            for (int i = 0; i < 2; i++)
#pragma unroll
                for (int j = 0; j < 8; j++)
#pragma unroll
                    for (int kq = 0; kq < 4; kq++) acc[i][j][kq] = 0.0f;

            MBARRIER_WAIT_PARITY(sb + 0, ph);
            prod64(AH, BH, wr, wc, lane, acc);
            MBARRIER_WAIT_PARITY(sb + 8, ph);
            prod64(AH, BL, wr, wc, lane, acc);
            prod64(AL, BH, wr, wc, lane, acc);
            ph ^= 1;
            __syncthreads();
            float* Cs = (float*)(smem + 1024);
            store_frag64(Cs, wr, wc, lane, acc);
            __syncthreads();
            if (lvl < 8) {
                float* Ug = g_U + (size_t)e * MSZ;
                for (int i = t * 4; i < MSZ; i += 1024)
                    *(float4*)&Ug[i] = *(const float4*)&Cs[i];
                __half* dst = g_B16 + (size_t)e * 32768;
                for (int item = t; item < 2048; item += 256) {
                    int n = item & 127, kb = item >> 7;
                    __half hv[8], lv[8];
#pragma unroll
                    for (int kk = 0; kk < 8; kk++) {
                        float v = Cs[(kb * 8 + kk) * DIM + n];
                        __half h = __float2half_rn(v);
                        hv[kk] = h;
                        lv[kk] = __float2half_rn(v - __half2float(h));
                    }
                    int k0 = kb * 8;
                    int idx = ((k0 >> 6) << 13) + (SW128(n * 128 + (k0 & 63) * 2) >> 1);
                    *(uint4*)&dst[idx] = *(uint4*)hv;
                    *(uint4*)&dst[idx + 16384] = *(uint4*)lv;
                }
            } else {
                __half* dst = g_A16 + (size_t)s * 16384;
                for (int item = t; item < 2048; item += 256) {
                    int kb = item & 15, m = item >> 4;
                    __half hv[8];
#pragma unroll
                    for (int kk = 0; kk < 8; kk++)
                        hv[kk] = __float2half_rn(Cs[m * DIM + kb * 8 + kk]);
                    int k0 = kb * 8;
                    int idx = ((k0 >> 6) << 13) + (SW128(m * 128 + (k0 & 63) * 2) >> 1);
                    *(uint4*)&dst[idx] = *(uint4*)hv;
                }
            }
        }
        if (lvl < 8) gbar_on(&g_count2, base + (unsigned)(++barId) * 128u);
    }
}

// ===========================================================================
// k_final: persistent, 152 CTAs, 8 compute warps + 1 producer warp.
// 2-slot ring, 96KB/slot: [A 32K][Bhi 32K][Blo 32K]. 2 products per position.
// ===========================================================================
#define SLOT_SZ 98304
#define FINAL_SMEM (1024 + 2 * SLOT_SZ)

__global__ void __launch_bounds__(288, 1) k_final(const int* __restrict__ uniq,
                                                  float* __restrict__ out, int n) {
    extern __shared__ char smem[];
    uint32_t sb = smem_to_u32(smem);
    int t = threadIdx.x;
    if (t == 0) {
#pragma unroll
        for (int s = 0; s < 2; s++) {
            MBARRIER_INIT(sb + s * 16, 1);        // full
            MBARRIER_INIT(sb + s * 16 + 8, 256);  // empty
        }
    }
    __syncthreads();

    if (t >= 256) {                 // producer warp
        if (t == 256) {
            unsigned u = 0;
            for (int i = blockIdx.x; i < n; i += gridDim.x) {
                int pos = __ldg(&uniq[i]);
                if (pos < 256) continue;
                int r = pos & 255, qi = (pos >> 8) - 1;
                unsigned s = u & 1, rd = u >> 1;
                if (u >= 2) MBARRIER_WAIT_PARITY(sb + s * 16 + 8, (rd - 1) & 1);
                MBARRIER_EXPECT_TX(sb + s * 16, 98304);
                uint32_t dst = sb + 1024 + s * SLOT_SZ;
                bulk_ld(dst,         g_A16 + (size_t)r * 16384,          32768, sb + s * 16);
                bulk_ld(dst + 32768, g_B16 + (size_t)qi * 32768,         32768, sb + s * 16);
                bulk_ld(dst + 65536, g_B16 + (size_t)qi * 32768 + 16384, 32768, sb + s * 16);
                u++;
            }
        }
        return;
    }

    int wid = t >> 5, lane = t & 31, wr = wid >> 1, wc = wid & 1;
    unsigned u = 0;
    for (int i = blockIdx.x; i < n; i += gridDim.x) {
        int pos = uniq[i];
        float* C = out + (size_t)i * MSZ;
        if (pos < 256) {
            const float* src = g_U + (size_t)(pos - 1) * MSZ;
            for (int e = t * 4; e < MSZ; e += 1024)
                *(float4*)&C[e] = *(const float4*)&src[e];
            continue;
        }
        unsigned s = u & 1, rd = u >> 1;
        u++;
        uint32_t basep = sb + 1024 + s * SLOT_SZ;

        float acc[2][8][4];
#pragma unroll
        for (int a = 0; a < 2; a++)
#pragma unroll
            for (int bq = 0; bq < 8; bq++)
#pragma unroll
                for (int c = 0; c < 4; c++) acc[a][bq][c] = 0.0f;

        MBARRIER_WAIT_PARITY(sb + s * 16, rd & 1);
        prod2_64(basep, basep + 32768, basep + 65536, wr, wc, lane, acc);
        MBARRIER_ARRIVE(sb + s * 16 + 8);
        store_frag64(C, wr, wc, lane, acc);
    }
}

// ===========================================================================
extern "C" void kernel_launch(void* const* d_in, const int* in_sizes, int n_in,
                              void* d_out, int out_size) {
    const int* uniq = (const int*)d_in[0];
    const float* P  = (const float*)d_in[1];
    float* out = (float*)d_out;
    int n = in_sizes[0];

    k_epoch<<<1, 1>>>();
    k_fused<<<dim3(32, 4), 256>>>(P);

    cudaFuncSetAttribute(k_levels, cudaFuncAttributeMaxDynamicSharedMemorySize, UL_SMEM);
    k_levels<<<128, 256, UL_SMEM>>>();

    cudaFuncSetAttribute(k_final, cudaFuncAttributeMaxDynamicSharedMemorySize, FINAL_SMEM);
    k_final<<<152, 288, FINAL_SMEM>>>(uniq, out, n);
}

// round 8
// speedup vs baseline: 1.4798x; 1.0778x over previous
#include <cuda_runtime.h>
#include <cuda_fp16.h>
#include <cstdint>

#define DIM 128
#define MSZ (DIM * DIM)

// fp32 tables for direct copies: g_U[e] = map for pos e+1, e in [0,254]
__device__ __align__(16) float g_U[255 * MSZ];
// fp16 images, chunked SW128 layout:
//  g_A16[s] : level-8 entry (pos 256+s), [m][k], HI ONLY (32KB = 16384 halfs)
//  g_B16[e] : U[e], [n][k], hi+lo (64KB): [hi c0 16K][hi c1 16K][lo c0][lo c1]
//  g_AW[b]  : W_b^T = U[1+b], [m][k], hi+lo
__device__ __align__(1024) __half g_A16[256 * 16384];
__device__ __align__(1024) __half g_B16[255 * 32768];
__device__ __align__(1024) __half g_AW[2 * 32768];
// expm scratch
__device__ __align__(16) float g_Bm[2 * MSZ];
__device__ __align__(16) float g_B2[2 * MSZ];
__device__ __align__(16) float g_B3[2 * MSZ];
__device__ __align__(16) float g_B4[2 * MSZ];
__device__ __align__(16) float g_X0[2 * MSZ];
__device__ __align__(16) float g_X1[2 * MSZ];
// global barrier state (monotonic across graph replays)
__device__ unsigned g_count = 0;   // k_fused
__device__ unsigned g_count2 = 0;  // k_levels
__device__ unsigned g_epoch = 0;

#define SW128(o) ((o) ^ (((o) >> 3) & 0x70))

// ------------------------------------------------------------- PTX helpers
__device__ __forceinline__ uint32_t smem_to_u32(const void* p) {
    uint32_t a;
    asm("{ .reg .u64 t; cvta.to.shared.u64 t, %1; cvt.u32.u64 %0, t; }" : "=r"(a) : "l"(p));
    return a;
}
#define MBARRIER_INIT(addr, cnt) \
    asm volatile("mbarrier.init.shared.b64 [%0], %1;" :: "r"((uint32_t)(addr)), "r"((uint32_t)(cnt)) : "memory")
#define MBARRIER_EXPECT_TX(addr, tx) \
    asm volatile("mbarrier.arrive.expect_tx.shared.b64 _, [%0], %1;" :: "r"((uint32_t)(addr)), "r"((uint32_t)(tx)) : "memory")
#define MBARRIER_ARRIVE(addr) \
    asm volatile("mbarrier.arrive.shared.b64 _, [%0];" :: "r"((uint32_t)(addr)) : "memory")
#define MBARRIER_WAIT_PARITY(mbar_smem_addr, phase_parity) do { \
    uint32_t _mbar = (uint32_t)(mbar_smem_addr); \
    uint32_t _parity = (uint32_t)(phase_parity); \
    uint32_t _done; \
    asm volatile("{\n\t.reg .pred p;\n\t" \
        "mbarrier.try_wait.parity.acquire.cta.shared::cta.b64 p, [%1], %2;\n\t" \
        "selp.b32 %0, 1, 0, p;\n\t}" : "=r"(_done) : "r"(_mbar), "r"(_parity) : "memory"); \
    if (!_done) { \
        asm volatile("{\n\t.reg .pred P1;\n\t" \
            "WAIT_LOOP_%=:\n\t" \
            "mbarrier.try_wait.parity.acquire.cta.shared::cta.b64 P1, [%0], %1, 0x989680;\n\t" \
            "@P1 bra.uni WAIT_DONE_%=;\n\t" \
            "bra.uni WAIT_LOOP_%=;\n\t" \
            "WAIT_DONE_%=:\n\t}" :: "r"(_mbar), "r"(_parity) : "memory"); \
    } \
} while (0)
__device__ __forceinline__ void bulk_ld(uint32_t dst, const void* src, uint32_t bytes, uint32_t mbar) {
    asm volatile("cp.async.bulk.shared::cta.global.mbarrier::complete_tx::bytes [%0], [%1], %2, [%3];"
                 :: "r"(dst), "l"(src), "r"(bytes), "r"(mbar) : "memory");
}
#define LDSM4(r0, r1, r2, r3, a) \
    asm volatile("ldmatrix.sync.aligned.m8n8.x4.shared.b16 {%0,%1,%2,%3}, [%4];" \
                 : "=r"(r0), "=r"(r1), "=r"(r2), "=r"(r3) : "r"(a))
#define MMA16816(c0, c1, c2, c3, a0, a1, a2, a3, b0, b1) \
    asm volatile("mma.sync.aligned.m16n8k16.row.col.f32.f16.f16.f32 " \
                 "{%0,%1,%2,%3}, {%4,%5,%6,%7}, {%8,%9}, {%0,%1,%2,%3};" \
                 : "+f"(c0), "+f"(c1), "+f"(c2), "+f"(c3) \
                 : "r"(a0), "r"(a1), "r"(a2), "r"(a3), "r"(b0), "r"(b1))

// hi/lo fp16 split write into a SW128 image
__device__ __forceinline__ void img_put(__half* img, int row, int k, float v) {
    int idx = ((k >> 6) << 13) + (SW128(row * 128 + (k & 63) * 2) >> 1);
    __half h = __float2half_rn(v);
    img[idx] = h;
    img[idx + 16384] = __float2half_rn(v - __half2float(h));
}

// ------------------------------------------------- global spin barriers
__device__ __forceinline__ void gbar_on(unsigned* ctr, unsigned target) {
    asm volatile("fence.proxy.async;" ::: "memory");
    __syncthreads();
    if (threadIdx.x == 0) {
        __threadfence();
        atomicAdd(ctr, 1u);
        unsigned v;
        do {
            asm volatile("ld.acquire.gpu.u32 %0, [%1];" : "=r"(v) : "l"(ctr) : "memory");
            if ((int)(v - target) >= 0) break;
            __nanosleep(64);
        } while (true);
    }
    __syncthreads();
}

// ------------------------------------- fp32 64x64 tile engine (.cg loads)
__device__ __forceinline__ void mm64cg(const float* __restrict__ A, const float* __restrict__ B,
                                       int rowBase, int colBase, float acc[4][4]) {
    __shared__ __align__(16) float As[16][64];
    __shared__ __align__(16) float Bs[16][64];
    int t = threadIdx.x;
    int tx = t & 15, ty = t >> 4;
#pragma unroll
    for (int i = 0; i < 4; i++)
#pragma unroll
        for (int j = 0; j < 4; j++) acc[i][j] = 0.0f;
    for (int kc = 0; kc < DIM; kc += 16) {
        {
            int ar = t >> 2, acg = (t & 3) * 4;
            float4 av = __ldcg((const float4*)&A[(rowBase + ar) * DIM + kc + acg]);
            As[acg + 0][ar] = av.x; As[acg + 1][ar] = av.y;
            As[acg + 2][ar] = av.z; As[acg + 3][ar] = av.w;
        }
        {
            int br = t >> 4, bcg = (t & 15) * 4;
            *(float4*)&Bs[br][bcg] = __ldcg((const float4*)&B[(kc + br) * DIM + colBase + bcg]);
        }
        __syncthreads();
#pragma unroll
        for (int kk = 0; kk < 16; kk++) {
            float a[4], bb[4];
            *(float4*)a  = *(const float4*)&As[kk][ty * 4];
            *(float4*)bb = *(const float4*)&Bs[kk][tx * 4];
#pragma unroll
            for (int i = 0; i < 4; i++)
#pragma unroll
                for (int j = 0; j < 4; j++) acc[i][j] += a[i] * bb[j];
        }
        __syncthreads();
    }
}
__device__ __forceinline__ void store64(float* __restrict__ C, int rowBase, int colBase,
                                        float acc[4][4]) {
    int tx = threadIdx.x & 15, ty = threadIdx.x >> 4;
#pragma unroll
    for (int i = 0; i < 4; i++)
#pragma unroll
        for (int j = 0; j < 4; j++)
            C[(rowBase + ty * 4 + i) * DIM + colBase + tx * 4 + j] = acc[i][j];
}

__global__ void k_epoch() { atomicAdd(&g_epoch, 1u); }

// -------------------------------------------------------------------------
// k_fused: prep -> B2,B3,B4 -> PS deg-16 -> 6 squarings -> init tables ->
//          levels 2..5 -> split (AW hi/lo + B16[0..62] hi/lo).  128 CTAs.
// -------------------------------------------------------------------------
#define NBAR 18u
__global__ void __launch_bounds__(256) k_fused(const float* __restrict__ P) {
    const int cta = blockIdx.y * 32 + blockIdx.x;   // 0..127
    const int t = threadIdx.x;
    __shared__ unsigned sE;
    if (t == 0) sE = *(volatile unsigned*)&g_epoch;
    __syncthreads();
    const unsigned base = (sE - 1u) * NBAR * 128u;
    int barId = 0;
#define GBAR() gbar_on(&g_count, base + (unsigned)(++barId) * 128u)

    const float c0 = 1.0f, c1 = 1.0f, c2 = 0.5f, c3 = 1.0f / 6.0f, c4 = 1.0f / 24.0f;
    const float c5 = 1.0f / 120.0f, c6 = 1.0f / 720.0f, c7 = 1.0f / 5040.0f;
    const float c8 = 1.0f / 40320.0f, c9 = 2.75573192e-6f, c10 = 2.75573192e-7f;
    const float c11 = 2.50521084e-8f, c12 = 2.08767570e-9f, c13 = 1.60590438e-10f;
    const float c14 = 1.14707456e-11f, c15 = 7.64716373e-13f, c16 = 4.77947733e-14f;

    {   // prep
        int idx = cta * 256 + t;
        int b = idx >> 14, r = (idx >> 7) & 127, c = idx & 127;
        float h = __ldg(&P[b * MSZ + r * DIM + c]) - __ldg(&P[b * MSZ + c * DIM + r]);
        g_Bm[idx] = h * (1.0f / 64.0f);
    }
    GBAR();
    if (cta < 8) {   // B2
        int b = cta >> 2, quad = cta & 3;
        int rB = (quad >> 1) * 64, cB = (quad & 1) * 64;
        float acc[4][4];
        mm64cg(g_Bm + b * MSZ, g_Bm + b * MSZ, rB, cB, acc);
        store64(g_B2 + b * MSZ, rB, cB, acc);
    }
    GBAR();
    if (cta < 16) {  // B3, B4
        int z = cta >> 3, b = (cta >> 2) & 1, quad = cta & 3;
        int rB = (quad >> 1) * 64, cB = (quad & 1) * 64;
        float acc[4][4];
        mm64cg(g_B2 + b * MSZ, (z ? g_B2 : g_Bm) + b * MSZ, rB, cB, acc);
        store64((z ? g_B4 : g_B3) + b * MSZ, rB, cB, acc);
    }
    GBAR();
    {   // PS init
        int idx = cta * 256 + t;
        int r = (idx >> 7) & 127, c = idx & 127;
        float v = c13 * __ldcg(&g_Bm[idx]) + c14 * __ldcg(&g_B2[idx]) +
                  c15 * __ldcg(&g_B3[idx]) + c16 * __ldcg(&g_B4[idx]);
        if (r == c) v += c12;
        g_X0[idx] = v;
    }
    GBAR();
    {
        float qs[3][4] = {{c8, c9, c10, c11}, {c4, c5, c6, c7}, {c0, c1, c2, c3}};
        int sel = 0;
        for (int h = 0; h < 3; h++) {
            if (cta < 8) {
                int b = cta >> 2, quad = cta & 3;
                int rB = (quad >> 1) * 64, cB = (quad & 1) * 64;
                const float* T = (sel ? g_X1 : g_X0) + b * MSZ;
                float* Y       = (sel ? g_X0 : g_X1) + b * MSZ;
                float acc[4][4];
                mm64cg(T, g_B4 + b * MSZ, rB, cB, acc);
                int tx = t & 15, ty = t >> 4;
#pragma unroll
                for (int i = 0; i < 4; i++) {
                    int gr = rB + ty * 4 + i;
#pragma unroll
                    for (int j = 0; j < 4; j++) {
                        int gc = cB + tx * 4 + j;
                        int e = b * MSZ + gr * DIM + gc;
                        float v = acc[i][j] + qs[h][1] * __ldcg(&g_Bm[e]) +
                                  qs[h][2] * __ldcg(&g_B2[e]) + qs[h][3] * __ldcg(&g_B3[e]);
                        if (gr == gc) v += qs[h][0];
                        Y[gr * DIM + gc] = v;
                    }
                }
            }
            sel ^= 1;
            GBAR();
        }
        for (int sq = 0; sq < 6; sq++) {
            if (cta < 8) {
                int b = cta >> 2, quad = cta & 3;
                int rB = (quad >> 1) * 64, cB = (quad & 1) * 64;
                const float* X = (sel ? g_X1 : g_X0) + b * MSZ;
                float* Y       = (sel ? g_X0 : g_X1) + b * MSZ;
                float acc[4][4];
                mm64cg(X, X, rB, cB, acc);
                store64(Y, rB, cB, acc);
            }
            sel ^= 1;
            GBAR();
        }
    }
    // init tables (E in X1): g_U[0]=I, g_U[1+b]=E_b^T
    for (int i = cta * 256 + t; i < 3 * MSZ; i += 32768) {
        int m = i >> 14, r = (i >> 7) & 127, c = i & 127;
        if (m == 0) g_U[i] = (r == c) ? 1.0f : 0.0f;
        else        g_U[m * MSZ + r * DIM + c] = __ldcg(&g_X1[(m - 1) * MSZ + c * DIM + r]);
    }
    GBAR();
    // levels 2..5
    for (int j = 2; j <= 5; j++) {
        if (cta < (4 << j)) {
            int s = cta >> 2, quad = cta & 3;
            int rB = (quad >> 1) * 64, cB = (quad & 1) * 64;
            const float* A = g_U + (size_t)(1 + (s & 1)) * MSZ;
            const float* B = g_U + (size_t)(((1 << (j - 1)) - 1) + (s >> 1)) * MSZ;
            float* C       = g_U + (size_t)(((1 << j) - 1) + s) * MSZ;
            float acc[4][4];
            mm64cg(A, B, rB, cB, acc);
            store64(C, rB, cB, acc);
        }
        GBAR();
    }
    // split phase: g_AW (U[1],U[2] as [m][k]) + g_B16[0..62] ([n][k]), fp16 hi/lo
    for (int item = cta * 256 + t; item < 2 * MSZ; item += 32768) {
        int mat = item >> 14, el = item & 16383, m = el >> 7, k = el & 127;
        float v = __ldcg(&g_U[(size_t)(1 + mat) * MSZ + m * DIM + k]);
        img_put(g_AW + (size_t)mat * 32768, m, k, v);
    }
    for (int item = cta * 256 + t; item < 63 * MSZ; item += 32768) {
        int mat = item >> 14, el = item & 16383, n = el & 127, k = el >> 7;
        float v = __ldcg(&g_U[(size_t)mat * MSZ + k * DIM + n]);
        img_put(g_B16 + (size_t)mat * 32768, n, k, v);
    }
#undef GBAR
}

// ===========================================================================
// HMMA engines.
// prod64: warp tile 32x64 (wr 0..3, wc 0..1) — used by k_levels (table build)
// ===========================================================================
__device__ __forceinline__ void prod64(uint32_t aimg, uint32_t bimg,
                                       int wr, int wc, int lane, float acc[2][8][4]) {
    int rA0 = (wr * 32 + (lane & 15)) * 128;
    int seg = (lane >> 4) * 16;
    int rB = (lane & 15) * 128;
#pragma unroll
    for (int ks = 0; ks < 8; ks++) {
        uint32_t coff = (uint32_t)(ks >> 2) * 16384u;
        int kw2 = (ks & 3) * 32;
        uint32_t a0, a1, a2, a3, a4, a5, a6, a7;
        LDSM4(a0, a1, a2, a3, aimg + coff + (uint32_t)SW128(rA0 + kw2 + seg));
        LDSM4(a4, a5, a6, a7, aimg + coff + (uint32_t)SW128(rA0 + 2048 + kw2 + seg));
#pragma unroll
        for (int ng = 0; ng < 4; ng++) {
            uint32_t b0, b1, b2, b3;
            LDSM4(b0, b1, b2, b3,
                  bimg + coff + (uint32_t)SW128((wc * 4 + ng) * 2048 + rB + kw2 + seg));
            MMA16816(acc[0][2 * ng][0], acc[0][2 * ng][1], acc[0][2 * ng][2], acc[0][2 * ng][3],
                     a0, a1, a2, a3, b0, b2);
            MMA16816(acc[0][2 * ng + 1][0], acc[0][2 * ng + 1][1], acc[0][2 * ng + 1][2], acc[0][2 * ng + 1][3],
                     a0, a1, a2, a3, b1, b3);
            MMA16816(acc[1][2 * ng][0], acc[1][2 * ng][1], acc[1][2 * ng][2], acc[1][2 * ng][3],
                     a4, a5, a6, a7, b0, b2);
            MMA16816(acc[1][2 * ng + 1][0], acc[1][2 * ng + 1][1], acc[1][2 * ng + 1][2], acc[1][2 * ng + 1][3],
                     a4, a5, a6, a7, b1, b3);
        }
    }
}
__device__ __forceinline__ void store_frag64(float* __restrict__ C, int wr, int wc, int lane,
                                             float acc[2][8][4]) {
#pragma unroll
    for (int rt = 0; rt < 2; rt++) {
        int row0 = wr * 32 + rt * 16 + (lane >> 2);
#pragma unroll
        for (int ct = 0; ct < 8; ct++) {
            int col = wc * 64 + ct * 8 + (lane & 3) * 2;
            *(float2*)&C[row0 * DIM + col]       = make_float2(acc[rt][ct][0], acc[rt][ct][1]);
            *(float2*)&C[(row0 + 8) * DIM + col] = make_float2(acc[rt][ct][2], acc[rt][ct][3]);
        }
    }
}

// ---------------------------------------------------------------------------
// prodT: warp tile 64x32 (wr 0..1 row bands, wc 0..3 col bands) — k_final.
// A hoisted per ks (4 LDSM), B hi then lo phases (8-MMA dependency spacing).
// acc[at][ct][4]: at = 16-row tile (0..3), ct = 8-col tile (0..3).
// ---------------------------------------------------------------------------
__device__ __forceinline__ void prodT(uint32_t aimg, uint32_t bhi, uint32_t blo,
                                      int wr, int wc, int lane, float acc[4][4][4]) {
    int rA = (wr * 64 + (lane & 15)) * 128;
    int seg = (lane >> 4) * 16;
    int rB = (wc * 32 + (lane & 15)) * 128;
#pragma unroll
    for (int ks = 0; ks < 8; ks++) {
        uint32_t coff = (uint32_t)(ks >> 2) * 16384u;
        int kw2 = (ks & 3) * 32;
        uint32_t a[4][4];
#pragma unroll
        for (int at = 0; at < 4; at++)
            LDSM4(a[at][0], a[at][1], a[at][2], a[at][3],
                  aimg + coff + (uint32_t)SW128(rA + at * 2048 + kw2 + seg));
        uint32_t b0[4], b1[4];
        LDSM4(b0[0], b0[1], b0[2], b0[3], bhi + coff + (uint32_t)SW128(rB + kw2 + seg));
        LDSM4(b1[0], b1[1], b1[2], b1[3], bhi + coff + (uint32_t)SW128(rB + 2048 + kw2 + seg));
#pragma unroll
        for (int at = 0; at < 4; at++) {
            MMA16816(acc[at][0][0], acc[at][0][1], acc[at][0][2], acc[at][0][3],
                     a[at][0], a[at][1], a[at][2], a[at][3], b0[0], b0[2]);
            MMA16816(acc[at][1][0], acc[at][1][1], acc[at][1][2], acc[at][1][3],
                     a[at][0], a[at][1], a[at][2], a[at][3], b0[1], b0[3]);
            MMA16816(acc[at][2][0], acc[at][2][1], acc[at][2][2], acc[at][2][3],
                     a[at][0], a[at][1], a[at][2], a[at][3], b1[0], b1[2]);
            MMA16816(acc[at][3][0], acc[at][3][1], acc[at][3][2], acc[at][3][3],
                     a[at][0], a[at][1], a[at][2], a[at][3], b1[1], b1[3]);
        }
        LDSM4(b0[0], b0[1], b0[2], b0[3], blo + coff + (uint32_t)SW128(rB + kw2 + seg));
        LDSM4(b1[0], b1[1], b1[2], b1[3], blo + coff + (uint32_t)SW128(rB + 2048 + kw2 + seg));
#pragma unroll
        for (int at = 0; at < 4; at++) {
            MMA16816(acc[at][0][0], acc[at][0][1], acc[at][0][2], acc[at][0][3],
                     a[at][0], a[at][1], a[at][2], a[at][3], b0[0], b0[2]);
            MMA16816(acc[at][1][0], acc[at][1][1], acc[at][1][2], acc[at][1][3],
                     a[at][0], a[at][1], a[at][2], a[at][3], b0[1], b0[3]);
            MMA16816(acc[at][2][0], acc[at][2][1], acc[at][2][2], acc[at][2][3],
                     a[at][0], a[at][1], a[at][2], a[at][3], b1[0], b1[2]);
            MMA16816(acc[at][3][0], acc[at][3][1], acc[at][3][2], acc[at][3][3],
                     a[at][0], a[at][1], a[at][2], a[at][3], b1[1], b1[3]);
        }
    }
}
__device__ __forceinline__ void store_fragT(float* __restrict__ C, int wr, int wc, int lane,
                                            float acc[4][4][4]) {
#pragma unroll
    for (int at = 0; at < 4; at++) {
        int row0 = wr * 64 + at * 16 + (lane >> 2);
#pragma unroll
        for (int ct = 0; ct < 4; ct++) {
            int col = wc * 32 + ct * 8 + (lane & 3) * 2;
            *(float2*)&C[row0 * DIM + col]       = make_float2(acc[at][ct][0], acc[at][ct][1]);
            *(float2*)&C[(row0 + 8) * DIM + col] = make_float2(acc[at][ct][2], acc[at][ct][3]);
        }
    }
}

// ===========================================================================
// k_levels: levels 6..8 in ONE launch. 128 persistent CTAs, 2 spin barriers.
// ===========================================================================
#define NBARL 2u
#define UL_SMEM (1024 + 131072)
__global__ void __launch_bounds__(256, 1) k_levels() {
    extern __shared__ char smem[];
    uint32_t sb = smem_to_u32(smem);
    const int cta = blockIdx.x;     // 0..127
    const int t = threadIdx.x, wid = t >> 5, lane = t & 31, wr = wid >> 1, wc = wid & 1;
    __shared__ unsigned sE;
    if (t == 0) sE = *(volatile unsigned*)&g_epoch;
    __syncthreads();
    const unsigned base = (sE - 1u) * NBARL * 128u;
    int barId = 0;
    if (t == 0) { MBARRIER_INIT(sb + 0, 1); MBARRIER_INIT(sb + 8, 1); }
    __syncthreads();
    uint32_t AH = sb + 1024, BH = AH + 32768, AL = BH + 32768, BL = AL + 32768;
    int ph = 0;

    for (int lvl = 6; lvl <= 8; lvl++) {
        int ntask = 1 << lvl;
        int offPrev = (1 << (lvl - 1)) - 1, offCur = (1 << lvl) - 1;
        for (int s = cta; s < ntask; s += 128) {
            __syncthreads();
            int e = offCur + s;
            const char* As = (const char*)(g_AW + (size_t)(s & 1) * 32768);
            const char* Bs = (const char*)(g_B16 + (size_t)(offPrev + (s >> 1)) * 32768);
            if (t == 0) {
                MBARRIER_EXPECT_TX(sb + 0, 65536);
                bulk_ld(AH, As, 32768, sb + 0);
                bulk_ld(BH, Bs, 32768, sb + 0);
                MBARRIER_EXPECT_TX(sb + 8, 65536);
                bulk_ld(AL, As + 32768, 32768, sb + 8);
                bulk_ld(BL, Bs + 32768, 32768, sb + 8);
            }
            float acc[2][8][4];
#pragma unroll
            for (int i = 0; i < 2; i++)
#pragma unroll
                for (int j = 0; j < 8; j++)
#pragma unroll
                    for (int kq = 0; kq < 4; kq++) acc[i][j][kq] = 0.0f;

            MBARRIER_WAIT_PARITY(sb + 0, ph);
            prod64(AH, BH, wr, wc, lane, acc);
            MBARRIER_WAIT_PARITY(sb + 8, ph);
            prod64(AH, BL, wr, wc, lane, acc);
            prod64(AL, BH, wr, wc, lane, acc);
            ph ^= 1;
            __syncthreads();
            float* Cs = (float*)(smem + 1024);
            store_frag64(Cs, wr, wc, lane, acc);
            __syncthreads();
            if (lvl < 8) {
                float* Ug = g_U + (size_t)e * MSZ;
                for (int i = t * 4; i < MSZ; i += 1024)
                    *(float4*)&Ug[i] = *(const float4*)&Cs[i];
                __half* dst = g_B16 + (size_t)e * 32768;
                for (int item = t; item < 2048; item += 256) {
                    int n = item & 127, kb = item >> 7;
                    __half hv[8], lv[8];
#pragma unroll
                    for (int kk = 0; kk < 8; kk++) {
                        float v = Cs[(kb * 8 + kk) * DIM + n];
                        __half h = __float2half_rn(v);
                        hv[kk] = h;
                        lv[kk] = __float2half_rn(v - __half2float(h));
                    }
                    int k0 = kb * 8;
                    int idx = ((k0 >> 6) << 13) + (SW128(n * 128 + (k0 & 63) * 2) >> 1);
                    *(uint4*)&dst[idx] = *(uint4*)hv;
                    *(uint4*)&dst[idx + 16384] = *(uint4*)lv;
                }
            } else {
                __half* dst = g_A16 + (size_t)s * 16384;
                for (int item = t; item < 2048; item += 256) {
                    int kb = item & 15, m = item >> 4;
                    __half hv[8];
#pragma unroll
                    for (int kk = 0; kk < 8; kk++)
                        hv[kk] = __float2half_rn(Cs[m * DIM + kb * 8 + kk]);
                    int k0 = kb * 8;
                    int idx = ((k0 >> 6) << 13) + (SW128(m * 128 + (k0 & 63) * 2) >> 1);
                    *(uint4*)&dst[idx] = *(uint4*)hv;
                }
            }
        }
        if (lvl < 8) gbar_on(&g_count2, base + (unsigned)(++barId) * 128u);
    }
}

// ===========================================================================
// k_final: persistent, 152 CTAs, 8 compute warps (64x32 tiles) + 1 producer.
// 2-slot ring, 96KB/slot: [A 32K][Bhi 32K][Blo 32K].
// ===========================================================================
#define SLOT_SZ 98304
#define FINAL_SMEM (1024 + 2 * SLOT_SZ)

__global__ void __launch_bounds__(288, 1) k_final(const int* __restrict__ uniq,
                                                  float* __restrict__ out, int n) {
    extern __shared__ char smem[];
    uint32_t sb = smem_to_u32(smem);
    int t = threadIdx.x;
    if (t == 0) {
#pragma unroll
        for (int s = 0; s < 2; s++) {
            MBARRIER_INIT(sb + s * 16, 1);        // full
            MBARRIER_INIT(sb + s * 16 + 8, 256);  // empty
        }
    }
    __syncthreads();

    if (t >= 256) {                 // producer warp
        if (t == 256) {
            unsigned u = 0;
            for (int i = blockIdx.x; i < n; i += gridDim.x) {
                int pos = __ldg(&uniq[i]);
                if (pos < 256) continue;
                int r = pos & 255, qi = (pos >> 8) - 1;
                unsigned s = u & 1, rd = u >> 1;
                if (u >= 2) MBARRIER_WAIT_PARITY(sb + s * 16 + 8, (rd - 1) & 1);
                MBARRIER_EXPECT_TX(sb + s * 16, 98304);
                uint32_t dst = sb + 1024 + s * SLOT_SZ;
                bulk_ld(dst,         g_A16 + (size_t)r * 16384,          32768, sb + s * 16);
                bulk_ld(dst + 32768, g_B16 + (size_t)qi * 32768,         32768, sb + s * 16);
                bulk_ld(dst + 65536, g_B16 + (size_t)qi * 32768 + 16384, 32768, sb + s * 16);
                u++;
            }
        }
        return;
    }

    int wid = t >> 5, lane = t & 31, wr = wid & 1, wc = wid >> 1;
    unsigned u = 0;
    for (int i = blockIdx.x; i < n; i += gridDim.x) {
        int pos = uniq[i];
        float* C = out + (size_t)i * MSZ;
        if (pos < 256) {
            const float* src = g_U + (size_t)(pos - 1) * MSZ;
            for (int e = t * 4; e < MSZ; e += 1024)
                *(float4*)&C[e] = *(const float4*)&src[e];
            continue;
        }
        unsigned s = u & 1, rd = u >> 1;
        u++;
        uint32_t basep = sb + 1024 + s * SLOT_SZ;

        float acc[4][4][4];
#pragma unroll
        for (int a = 0; a < 4; a++)
#pragma unroll
            for (int bq = 0; bq < 4; bq++)
#pragma unroll
                for (int c = 0; c < 4; c++) acc[a][bq][c] = 0.0f;

        MBARRIER_WAIT_PARITY(sb + s * 16, rd & 1);
        prodT(basep, basep + 32768, basep + 65536, wr, wc, lane, acc);
        MBARRIER_ARRIVE(sb + s * 16 + 8);
        store_fragT(C, wr, wc, lane, acc);
    }
}

// ===========================================================================
extern "C" void kernel_launch(void* const* d_in, const int* in_sizes, int n_in,
                              void* d_out, int out_size) {
    const int* uniq = (const int*)d_in[0];
    const float* P  = (const float*)d_in[1];
    float* out = (float*)d_out;
    int n = in_sizes[0];

    k_epoch<<<1, 1>>>();
    k_fused<<<dim3(32, 4), 256>>>(P);

    cudaFuncSetAttribute(k_levels, cudaFuncAttributeMaxDynamicSharedMemorySize, UL_SMEM);
    k_levels<<<128, 256, UL_SMEM>>>();

    cudaFuncSetAttribute(k_final, cudaFuncAttributeMaxDynamicSharedMemorySize, FINAL_SMEM);
    k_final<<<152, 288, FINAL_SMEM>>>(uniq, out, n);
}